// round 1
// baseline (speedup 1.0000x reference)
#include <cuda_runtime.h>

#define Bb 64
#define Nn 512
#define Ff 16
#define Tt 288

// ---------------- scratch (static device globals; no allocs) ----------------
__device__ float g_y [Bb * Nn * Ff];               // y[b,n,f]  = sum_t x*W1
__device__ float g_zz[Bb * Nn * Ff];               // zz[b,m,f] = sum_t W2[f,t]*rhs[b,m,t]
__device__ float g_sg[(size_t)Bb * Nn * Nn];       // sigmoid(product + b_s)

// ---------------------------------------------------------------------------
// K1: per (b,n) block, 288 threads.
//   load x[b,n,:,:] (16x288) to smem (coalesced float4)
//   rs[t] = sum_f x[f][t]*W3[f]            (rhs, kept in smem)
//   y[f]  = sum_t x[f][t]*W1[t]            (warp reductions)
//   zz[f] = sum_t W2[f][t]*rs[t]           (warp reductions)
// ---------------------------------------------------------------------------
__global__ __launch_bounds__(288) void k1_kernel(const float* __restrict__ x,
                                                 const float* __restrict__ W1,
                                                 const float* __restrict__ W2,
                                                 const float* __restrict__ W3) {
    __shared__ float xs[Ff * Tt];
    __shared__ float rs[Tt];
    __shared__ float w1s[Tt];
    __shared__ float w3s[Ff];
    __shared__ float red[Ff];

    const int tid = threadIdx.x;
    const int bn  = blockIdx.x;

    const float4* xp4 = reinterpret_cast<const float4*>(x + (size_t)bn * (Ff * Tt));
    float4* xs4 = reinterpret_cast<float4*>(xs);
#pragma unroll
    for (int i = 0; i < 4; i++) xs4[tid + Tt * i] = xp4[tid + Tt * i];
    w1s[tid] = W1[tid];
    if (tid < Ff) w3s[tid] = W3[tid];
    __syncthreads();

    // rhs over t (thread = t)
    float r = 0.f;
#pragma unroll
    for (int f = 0; f < Ff; f++) r += xs[f * Tt + tid] * w3s[f];
    rs[tid] = r;

    const int w = tid >> 5, l = tid & 31;

    // y[f] warp reductions (9 warps cover f = w and w+9)
    for (int f = w; f < Ff; f += 9) {
        float p = 0.f;
#pragma unroll
        for (int c = 0; c < 9; c++) p += xs[f * Tt + l + 32 * c] * w1s[l + 32 * c];
#pragma unroll
        for (int o = 16; o > 0; o >>= 1) p += __shfl_down_sync(0xffffffffu, p, o);
        if (l == 0) red[f] = p;
    }
    __syncthreads();

    if (tid < Ff) g_y[(size_t)bn * Ff + tid] = red[tid];

    // zz[f] warp reductions (W2 reads are warp-coalesced, L2-resident)
    for (int f = w; f < Ff; f += 9) {
        float p = 0.f;
#pragma unroll
        for (int c = 0; c < 9; c++) p += W2[f * Tt + l + 32 * c] * rs[l + 32 * c];
#pragma unroll
        for (int o = 16; o > 0; o >>= 1) p += __shfl_down_sync(0xffffffffu, p, o);
        if (l == 0) g_zz[(size_t)bn * Ff + f] = p;
    }
}

// ---------------------------------------------------------------------------
// K2: Sg[b,n,m] = sigmoid( dot16(y[b,n,:], zz[b,m,:]) + b_s[n,m] )
//   tile: 8 n-rows x 128 m-cols per block, 256 threads, 1 float4 output each.
// ---------------------------------------------------------------------------
__global__ __launch_bounds__(256) void k2_kernel(const float* __restrict__ bs) {
    __shared__ float ys[8][Ff];
    __shared__ float zs[Ff][132];   // [f][m], pad 132 for bank behavior + f4 alignment

    const int tid = threadIdx.x;
    const int m0  = blockIdx.x * 128;
    const int n0  = blockIdx.y * 8;
    const int b   = blockIdx.z;

    if (tid < 128)
        ys[tid >> 4][tid & 15] = g_y[((size_t)b * Nn + n0) * Ff + tid];

    const float4* zz4 = reinterpret_cast<const float4*>(g_zz + ((size_t)b * Nn + m0) * Ff);
#pragma unroll
    for (int i = 0; i < 2; i++) {
        int q = tid + 256 * i;
        int m = q >> 2, fq = q & 3;
        float4 v = zz4[q];
        zs[fq * 4 + 0][m] = v.x;
        zs[fq * 4 + 1][m] = v.y;
        zs[fq * 4 + 2][m] = v.z;
        zs[fq * 4 + 3][m] = v.w;
    }
    __syncthreads();

    const int m4 = tid & 31, nq = tid >> 5;
    float4 acc = *reinterpret_cast<const float4*>(bs + (size_t)(n0 + nq) * Nn + m0 + m4 * 4);
#pragma unroll
    for (int f = 0; f < Ff; f++) {
        float yf = ys[nq][f];
        float4 z = *reinterpret_cast<const float4*>(&zs[f][m4 * 4]);
        acc.x += yf * z.x;
        acc.y += yf * z.y;
        acc.z += yf * z.z;
        acc.w += yf * z.w;
    }
    acc.x = 1.f / (1.f + __expf(-acc.x));
    acc.y = 1.f / (1.f + __expf(-acc.y));
    acc.z = 1.f / (1.f + __expf(-acc.z));
    acc.w = 1.f / (1.f + __expf(-acc.w));

    float4* op = reinterpret_cast<float4*>(g_sg + (((size_t)b * Nn + n0 + nq) * Nn + m0)) + m4;
    *op = acc;
}

// ---------------------------------------------------------------------------
// K3: s[b] = Sg[b] (512x512) @ V_s^T (512x512)  -> written raw into d_out
//   128x128 block tile, Kb=16, 256 threads, 8x8 micro-tile, global prefetch.
// ---------------------------------------------------------------------------
__global__ __launch_bounds__(256) void k3_kernel(const float* __restrict__ Vs,
                                                 float* __restrict__ out) {
    __shared__ float As[16][132];
    __shared__ float Bs[16][132];

    const int tid = threadIdx.x;
    const int it  = blockIdx.x;   // i tile (cols)
    const int nt  = blockIdx.y;   // n tile (rows)
    const int b   = blockIdx.z;

    const float* A  = g_sg + (size_t)b * Nn * Nn + (size_t)nt * 128 * Nn;
    const float* Bm = Vs + (size_t)it * 128 * Nn;

    const int tx = tid & 15, ty = tid >> 4;
    const int row = tid >> 2;    // 0..63 (second half at row+64)
    const int kq  = tid & 3;

    float acc[8][8];
#pragma unroll
    for (int i = 0; i < 8; i++)
#pragma unroll
        for (int j = 0; j < 8; j++) acc[i][j] = 0.f;

    float4 pa0 = *reinterpret_cast<const float4*>(A  + (size_t)row * Nn + kq * 4);
    float4 pa1 = *reinterpret_cast<const float4*>(A  + (size_t)(row + 64) * Nn + kq * 4);
    float4 pb0 = *reinterpret_cast<const float4*>(Bm + (size_t)row * Nn + kq * 4);
    float4 pb1 = *reinterpret_cast<const float4*>(Bm + (size_t)(row + 64) * Nn + kq * 4);

    for (int k0 = 0; k0 < Nn; k0 += 16) {
        __syncthreads();
        As[kq * 4 + 0][row] = pa0.x;  As[kq * 4 + 1][row] = pa0.y;
        As[kq * 4 + 2][row] = pa0.z;  As[kq * 4 + 3][row] = pa0.w;
        As[kq * 4 + 0][row + 64] = pa1.x;  As[kq * 4 + 1][row + 64] = pa1.y;
        As[kq * 4 + 2][row + 64] = pa1.z;  As[kq * 4 + 3][row + 64] = pa1.w;
        Bs[kq * 4 + 0][row] = pb0.x;  Bs[kq * 4 + 1][row] = pb0.y;
        Bs[kq * 4 + 2][row] = pb0.z;  Bs[kq * 4 + 3][row] = pb0.w;
        Bs[kq * 4 + 0][row + 64] = pb1.x;  Bs[kq * 4 + 1][row + 64] = pb1.y;
        Bs[kq * 4 + 2][row + 64] = pb1.z;  Bs[kq * 4 + 3][row + 64] = pb1.w;
        __syncthreads();

        if (k0 + 16 < Nn) {   // prefetch next slab (hides gmem latency behind FMAs)
            pa0 = *reinterpret_cast<const float4*>(A  + (size_t)row * Nn + k0 + 16 + kq * 4);
            pa1 = *reinterpret_cast<const float4*>(A  + (size_t)(row + 64) * Nn + k0 + 16 + kq * 4);
            pb0 = *reinterpret_cast<const float4*>(Bm + (size_t)row * Nn + k0 + 16 + kq * 4);
            pb1 = *reinterpret_cast<const float4*>(Bm + (size_t)(row + 64) * Nn + k0 + 16 + kq * 4);
        }

#pragma unroll
        for (int k = 0; k < 16; k++) {
            float a[8], bb[8];
            *reinterpret_cast<float4*>(a)      = *reinterpret_cast<const float4*>(&As[k][ty * 8]);
            *reinterpret_cast<float4*>(a + 4)  = *reinterpret_cast<const float4*>(&As[k][ty * 8 + 4]);
            *reinterpret_cast<float4*>(bb)     = *reinterpret_cast<const float4*>(&Bs[k][tx * 8]);
            *reinterpret_cast<float4*>(bb + 4) = *reinterpret_cast<const float4*>(&Bs[k][tx * 8 + 4]);
#pragma unroll
            for (int i = 0; i < 8; i++)
#pragma unroll
                for (int j = 0; j < 8; j++) acc[i][j] += a[i] * bb[j];
        }
    }

    float* outb = out + (size_t)b * Nn * Nn + (size_t)(nt * 128 + ty * 8) * Nn + it * 128 + tx * 8;
#pragma unroll
    for (int i = 0; i < 8; i++) {
        float4 v0 = make_float4(acc[i][0], acc[i][1], acc[i][2], acc[i][3]);
        float4 v1 = make_float4(acc[i][4], acc[i][5], acc[i][6], acc[i][7]);
        *reinterpret_cast<float4*>(outb + (size_t)i * Nn)     = v0;
        *reinterpret_cast<float4*>(outb + (size_t)i * Nn + 4) = v1;
    }
}

// ---------------------------------------------------------------------------
// K4: in-place softmax over axis 1 (n) of d_out[b,n,i].
//   block = (batch b, 32 columns i); 8 segments of 64 rows per column.
// ---------------------------------------------------------------------------
__global__ __launch_bounds__(256) void k4_kernel(float* __restrict__ out) {
    const int tid = threadIdx.x;
    const int col = tid & 31, seg = tid >> 5;
    const int i0  = blockIdx.x * 32;
    const int b   = blockIdx.y;

    float* base = out + (size_t)b * Nn * Nn + i0 + col;

    float m = -1e30f, s = 0.f;
    for (int n = seg * 64; n < seg * 64 + 64; n++) {
        float v  = base[(size_t)n * Nn];
        float mn = fmaxf(m, v);
        s = s * __expf(m - mn) + __expf(v - mn);
        m = mn;
    }

    __shared__ float sm[8][32], ssum[8][32];
    sm[seg][col]   = m;
    ssum[seg][col] = s;
    __syncthreads();

    float M = -1e30f;
#pragma unroll
    for (int g = 0; g < 8; g++) M = fmaxf(M, sm[g][col]);
    float S = 0.f;
#pragma unroll
    for (int g = 0; g < 8; g++) S += ssum[g][col] * __expf(sm[g][col] - M);
    float invS = 1.f / S;

    for (int n = seg * 64; n < seg * 64 + 64; n++) {
        float v = base[(size_t)n * Nn];
        base[(size_t)n * Nn] = __expf(v - M) * invS;
    }
}

// ---------------------------------------------------------------------------
extern "C" void kernel_launch(void* const* d_in, const int* in_sizes, int n_in,
                              void* d_out, int out_size) {
    const float* x  = (const float*)d_in[0];   // (64,512,16,288)
    const float* W1 = (const float*)d_in[1];   // (288,)
    const float* W2 = (const float*)d_in[2];   // (16,288)
    const float* W3 = (const float*)d_in[3];   // (16,)
    const float* bs = (const float*)d_in[4];   // (1,512,512)
    const float* Vs = (const float*)d_in[5];   // (512,512)
    float* out = (float*)d_out;                // (64,512,512)

    k1_kernel<<<Bb * Nn, 288>>>(x, W1, W2, W3);
    k2_kernel<<<dim3(Nn / 128, Nn / 8, Bb), 256>>>(bs);
    k3_kernel<<<dim3(Nn / 128, Nn / 128, Bb), 256>>>(Vs, out);
    k4_kernel<<<dim3(Nn / 32, Bb), 256>>>(out);
}

// round 3
// speedup vs baseline: 1.7461x; 1.7461x over previous
#include <cuda_runtime.h>
#include <cuda_bf16.h>
#include <cstdint>

#define Bb 64
#define Nn 512
#define Ff 16
#define Tt 288

// ---------------- scratch (static device globals; no allocs) ----------------
__device__ float g_y [Bb * Nn * Ff];
__device__ float g_zz[Bb * Nn * Ff];
__device__ __nv_bfloat16 g_sg_hi[(size_t)Bb * Nn * Nn];
__device__ __nv_bfloat16 g_sg_lo[(size_t)Bb * Nn * Nn];
__device__ __nv_bfloat16 g_vs_hi[Nn * Nn];
__device__ __nv_bfloat16 g_vs_lo[Nn * Nn];

// ------------------------------- PTX helpers --------------------------------
__device__ __forceinline__ uint32_t smem_u32(const void* p) {
    uint32_t a;
    asm("{ .reg .u64 t; cvta.to.shared.u64 t, %1; cvt.u32.u64 %0, t; }" : "=r"(a) : "l"(p));
    return a;
}
__device__ __forceinline__ void cp16(uint32_t dst, const void* src) {
    asm volatile("cp.async.cg.shared.global [%0], [%1], 16;" :: "r"(dst), "l"(src) : "memory");
}
__device__ __forceinline__ void ldm_x4(uint32_t* r, uint32_t addr) {
    asm volatile("ldmatrix.sync.aligned.m8n8.x4.shared.b16 {%0,%1,%2,%3}, [%4];"
                 : "=r"(r[0]), "=r"(r[1]), "=r"(r[2]), "=r"(r[3]) : "r"(addr));
}
__device__ __forceinline__ void ldm_x2(uint32_t* r, uint32_t addr) {
    asm volatile("ldmatrix.sync.aligned.m8n8.x2.shared.b16 {%0,%1}, [%2];"
                 : "=r"(r[0]), "=r"(r[1]) : "r"(addr));
}
__device__ __forceinline__ void mma16816(float* d, const uint32_t* a, const uint32_t* bb) {
    asm volatile(
        "mma.sync.aligned.m16n8k16.row.col.f32.bf16.bf16.f32 "
        "{%0,%1,%2,%3}, {%4,%5,%6,%7}, {%8,%9}, {%0,%1,%2,%3};"
        : "+f"(d[0]), "+f"(d[1]), "+f"(d[2]), "+f"(d[3])
        : "r"(a[0]), "r"(a[1]), "r"(a[2]), "r"(a[3]), "r"(bb[0]), "r"(bb[1]));
}

// ---------------------------------------------------------------------------
// K1: per (b,n) block, 288 threads: y, zz from x (rank-16 factorization).
// ---------------------------------------------------------------------------
__global__ __launch_bounds__(288) void k1_kernel(const float* __restrict__ x,
                                                 const float* __restrict__ W1,
                                                 const float* __restrict__ W2,
                                                 const float* __restrict__ W3) {
    __shared__ float xs[Ff * Tt];
    __shared__ float rs[Tt];
    __shared__ float w1s[Tt];
    __shared__ float w3s[Ff];
    __shared__ float red[Ff];

    const int tid = threadIdx.x;
    const int bn  = blockIdx.x;

    const float4* xp4 = reinterpret_cast<const float4*>(x + (size_t)bn * (Ff * Tt));
    float4* xs4 = reinterpret_cast<float4*>(xs);
#pragma unroll
    for (int i = 0; i < 4; i++) xs4[tid + Tt * i] = xp4[tid + Tt * i];
    w1s[tid] = W1[tid];
    if (tid < Ff) w3s[tid] = W3[tid];
    __syncthreads();

    float r = 0.f;
#pragma unroll
    for (int f = 0; f < Ff; f++) r += xs[f * Tt + tid] * w3s[f];
    rs[tid] = r;

    const int w = tid >> 5, l = tid & 31;

    for (int f = w; f < Ff; f += 9) {
        float p = 0.f;
#pragma unroll
        for (int c = 0; c < 9; c++) p += xs[f * Tt + l + 32 * c] * w1s[l + 32 * c];
#pragma unroll
        for (int o = 16; o > 0; o >>= 1) p += __shfl_down_sync(0xffffffffu, p, o);
        if (l == 0) red[f] = p;
    }
    __syncthreads();

    if (tid < Ff) g_y[(size_t)bn * Ff + tid] = red[tid];

    for (int f = w; f < Ff; f += 9) {
        float p = 0.f;
#pragma unroll
        for (int c = 0; c < 9; c++) p += W2[f * Tt + l + 32 * c] * rs[l + 32 * c];
#pragma unroll
        for (int o = 16; o > 0; o >>= 1) p += __shfl_down_sync(0xffffffffu, p, o);
        if (l == 0) g_zz[(size_t)bn * Ff + f] = p;
    }
}

// ---------------------------------------------------------------------------
// KVS: split V_s (512x512 fp32) into bf16 hi/lo.
// ---------------------------------------------------------------------------
__global__ __launch_bounds__(256) void kvs_kernel(const float* __restrict__ Vs) {
    int i = blockIdx.x * 256 + threadIdx.x;
    float v = Vs[i];
    __nv_bfloat16 hi = __float2bfloat16(v);
    __nv_bfloat16 lo = __float2bfloat16(v - __bfloat162float(hi));
    g_vs_hi[i] = hi;
    g_vs_lo[i] = lo;
}

// ---------------------------------------------------------------------------
// K2: Sg = sigmoid(y . zz + b_s), written as bf16 hi/lo split.
// ---------------------------------------------------------------------------
__global__ __launch_bounds__(256) void k2_kernel(const float* __restrict__ bs) {
    __shared__ float ys[8][Ff];
    __shared__ float zs[Ff][132];

    const int tid = threadIdx.x;
    const int m0  = blockIdx.x * 128;
    const int n0  = blockIdx.y * 8;
    const int b   = blockIdx.z;

    if (tid < 128)
        ys[tid >> 4][tid & 15] = g_y[((size_t)b * Nn + n0) * Ff + tid];

    const float4* zz4 = reinterpret_cast<const float4*>(g_zz + ((size_t)b * Nn + m0) * Ff);
#pragma unroll
    for (int i = 0; i < 2; i++) {
        int q = tid + 256 * i;
        int m = q >> 2, fq = q & 3;
        float4 v = zz4[q];
        zs[fq * 4 + 0][m] = v.x;
        zs[fq * 4 + 1][m] = v.y;
        zs[fq * 4 + 2][m] = v.z;
        zs[fq * 4 + 3][m] = v.w;
    }
    __syncthreads();

    const int m4 = tid & 31, nq = tid >> 5;
    float4 acc = *reinterpret_cast<const float4*>(bs + (size_t)(n0 + nq) * Nn + m0 + m4 * 4);
#pragma unroll
    for (int f = 0; f < Ff; f++) {
        float yf = ys[nq][f];
        float4 z = *reinterpret_cast<const float4*>(&zs[f][m4 * 4]);
        acc.x += yf * z.x;
        acc.y += yf * z.y;
        acc.z += yf * z.z;
        acc.w += yf * z.w;
    }
    acc.x = 1.f / (1.f + __expf(-acc.x));
    acc.y = 1.f / (1.f + __expf(-acc.y));
    acc.z = 1.f / (1.f + __expf(-acc.z));
    acc.w = 1.f / (1.f + __expf(-acc.w));

    __nv_bfloat16 h0 = __float2bfloat16(acc.x);
    __nv_bfloat16 h1 = __float2bfloat16(acc.y);
    __nv_bfloat16 h2 = __float2bfloat16(acc.z);
    __nv_bfloat16 h3 = __float2bfloat16(acc.w);
    __nv_bfloat16 l0 = __float2bfloat16(acc.x - __bfloat162float(h0));
    __nv_bfloat16 l1 = __float2bfloat16(acc.y - __bfloat162float(h1));
    __nv_bfloat16 l2 = __float2bfloat16(acc.z - __bfloat162float(h2));
    __nv_bfloat16 l3 = __float2bfloat16(acc.w - __bfloat162float(h3));

    size_t base = ((size_t)b * Nn + n0 + nq) * Nn + m0;
    __nv_bfloat162* dh = reinterpret_cast<__nv_bfloat162*>(g_sg_hi + base) + m4 * 2;
    __nv_bfloat162* dl = reinterpret_cast<__nv_bfloat162*>(g_sg_lo + base) + m4 * 2;
    dh[0] = __halves2bfloat162(h0, h1);
    dh[1] = __halves2bfloat162(h2, h3);
    dl[0] = __halves2bfloat162(l0, l1);
    dl[1] = __halves2bfloat162(l2, l3);
}

// ---------------------------------------------------------------------------
// K3: s[b] = Sg[b] @ V_s^T via mma.sync bf16 (3-way split, fp32 accumulate).
//   128x128 tile / CTA, 8 warps (2x4), K chunks of 64, cp.async double buffer.
//   smem per array: 128 rows x 72 bf16 (144 B stride; 16B-aligned, no swizzle).
// ---------------------------------------------------------------------------
#define K3_STRIDE 144                      // bytes per smem row (64 bf16 + 8 pad)
#define K3_ARR    (128 * K3_STRIDE)        // 18432 B per array
#define K3_A_HI   0
#define K3_A_LO   (1 * K3_ARR)
#define K3_B_HI   (2 * K3_ARR)
#define K3_B_LO   (3 * K3_ARR)
#define K3_STAGE  (4 * K3_ARR)             // 73728 B
#define K3_SMEM   (2 * K3_STAGE)           // 147456 B

extern __shared__ char k3_smem[];

__global__ void __launch_bounds__(256, 1) k3_kernel(float* __restrict__ out) {
    const int tid  = threadIdx.x;
    const int wid  = tid >> 5;
    const int lane = tid & 31;
    const int i0   = blockIdx.x * 128;
    const int n0   = blockIdx.y * 128;
    const int b    = blockIdx.z;

    const uint32_t sbase = smem_u32(k3_smem);

    const __nv_bfloat16* Ahi = g_sg_hi + ((size_t)b * Nn + n0) * Nn;
    const __nv_bfloat16* Alo = g_sg_lo + ((size_t)b * Nn + n0) * Nn;
    const __nv_bfloat16* Bhi = g_vs_hi + (size_t)i0 * Nn;
    const __nv_bfloat16* Blo = g_vs_lo + (size_t)i0 * Nn;

    const int wr = wid >> 2;   // 0..1 : row half (64 rows)
    const int wc = wid & 3;    // 0..3 : col quarter (32 cols)

    // ldmatrix per-lane address offsets (bytes) within an array
    const int am = lane >> 3;                    // matrix index 0..3 (x4)
    const uint32_t aoff = (uint32_t)(((am & 1) * 8 + (lane & 7)) * K3_STRIDE + (am >> 1) * 16)
                        + (uint32_t)(wr * 64 * K3_STRIDE);
    const int bl = lane & 15;                    // x2 uses lanes 0..15
    const uint32_t boff = (uint32_t)((bl & 7) * K3_STRIDE + ((bl >> 3) & 1) * 16)
                        + (uint32_t)(wc * 32 * K3_STRIDE);

    float acc[4][4][4];
#pragma unroll
    for (int mi = 0; mi < 4; mi++)
#pragma unroll
        for (int ni = 0; ni < 4; ni++)
#pragma unroll
            for (int q = 0; q < 4; q++) acc[mi][ni][q] = 0.f;

#define K3_LOAD(CHUNK, STAGE)                                                      \
    do {                                                                           \
        const int k0_ = (CHUNK) * 64;                                              \
        const uint32_t st_ = sbase + (STAGE) * K3_STAGE;                           \
        _Pragma("unroll")                                                          \
        for (int i_ = 0; i_ < 4; i_++) {                                           \
            int idx_ = tid + 256 * i_;                                             \
            int row_ = idx_ >> 3, cc_ = idx_ & 7;                                  \
            uint32_t so_ = (uint32_t)(row_ * K3_STRIDE + cc_ * 16);                \
            size_t go_ = (size_t)row_ * Nn + k0_ + cc_ * 8;                        \
            cp16(st_ + K3_A_HI + so_, Ahi + go_);                                  \
            cp16(st_ + K3_A_LO + so_, Alo + go_);                                  \
            cp16(st_ + K3_B_HI + so_, Bhi + go_);                                  \
            cp16(st_ + K3_B_LO + so_, Blo + go_);                                  \
        }                                                                          \
        asm volatile("cp.async.commit_group;" ::: "memory");                       \
    } while (0)

    K3_LOAD(0, 0);

    for (int c = 0; c < 8; c++) {
        if (c + 1 < 8) {
            K3_LOAD(c + 1, (c + 1) & 1);
            asm volatile("cp.async.wait_group 1;" ::: "memory");
        } else {
            asm volatile("cp.async.wait_group 0;" ::: "memory");
        }
        __syncthreads();

        const uint32_t st = sbase + (c & 1) * K3_STAGE;
#pragma unroll
        for (int pass = 0; pass < 3; pass++) {
            const uint32_t Ab = st + (pass == 1 ? K3_A_LO : K3_A_HI) + aoff;
            const uint32_t Bbp = st + (pass == 2 ? K3_B_LO : K3_B_HI) + boff;
#pragma unroll
            for (int ks = 0; ks < 4; ks++) {
                uint32_t a[4][4];
#pragma unroll
                for (int mi = 0; mi < 4; mi++)
                    ldm_x4(a[mi], Ab + (uint32_t)(mi * 16 * K3_STRIDE + ks * 32));
                uint32_t bf[4][2];
#pragma unroll
                for (int ni = 0; ni < 4; ni++)
                    ldm_x2(bf[ni], Bbp + (uint32_t)(ni * 8 * K3_STRIDE + ks * 32));
#pragma unroll
                for (int mi = 0; mi < 4; mi++)
#pragma unroll
                    for (int ni = 0; ni < 4; ni++)
                        mma16816(acc[mi][ni], a[mi], bf[ni]);
            }
        }
        __syncthreads();
    }
#undef K3_LOAD

    // epilogue: m16n8 fragment layout -> global
    const int rr = lane >> 2;            // 0..7
    const int cc = (lane & 3) * 2;
#pragma unroll
    for (int mi = 0; mi < 4; mi++) {
#pragma unroll
        for (int ni = 0; ni < 4; ni++) {
            int row = n0 + wr * 64 + mi * 16 + rr;
            int col = i0 + wc * 32 + ni * 8 + cc;
            float* p0 = out + ((size_t)b * Nn + row) * Nn + col;
            float* p1 = out + ((size_t)b * Nn + row + 8) * Nn + col;
            *reinterpret_cast<float2*>(p0) = make_float2(acc[mi][ni][0], acc[mi][ni][1]);
            *reinterpret_cast<float2*>(p1) = make_float2(acc[mi][ni][2], acc[mi][ni][3]);
        }
    }
}

// ---------------------------------------------------------------------------
// K4: in-place softmax over axis 1 (n) of d_out[b,n,i].
// ---------------------------------------------------------------------------
__global__ __launch_bounds__(256) void k4_kernel(float* __restrict__ out) {
    const int tid = threadIdx.x;
    const int col = tid & 31, seg = tid >> 5;
    const int i0  = blockIdx.x * 32;
    const int b   = blockIdx.y;

    float* base = out + (size_t)b * Nn * Nn + i0 + col;

    float m = -1e30f, s = 0.f;
    for (int n = seg * 64; n < seg * 64 + 64; n++) {
        float v  = base[(size_t)n * Nn];
        float mn = fmaxf(m, v);
        s = s * __expf(m - mn) + __expf(v - mn);
        m = mn;
    }

    __shared__ float sm[8][32], ssum[8][32];
    sm[seg][col]   = m;
    ssum[seg][col] = s;
    __syncthreads();

    float M = -1e30f;
#pragma unroll
    for (int g = 0; g < 8; g++) M = fmaxf(M, sm[g][col]);
    float S = 0.f;
#pragma unroll
    for (int g = 0; g < 8; g++) S += ssum[g][col] * __expf(sm[g][col] - M);
    float invS = 1.f / S;

    for (int n = seg * 64; n < seg * 64 + 64; n++) {
        float v = base[(size_t)n * Nn];
        base[(size_t)n * Nn] = __expf(v - M) * invS;
    }
}

// ---------------------------------------------------------------------------
extern "C" void kernel_launch(void* const* d_in, const int* in_sizes, int n_in,
                              void* d_out, int out_size) {
    const float* x  = (const float*)d_in[0];   // (64,512,16,288)
    const float* W1 = (const float*)d_in[1];   // (288,)
    const float* W2 = (const float*)d_in[2];   // (16,288)
    const float* W3 = (const float*)d_in[3];   // (16,)
    const float* bs = (const float*)d_in[4];   // (1,512,512)
    const float* Vs = (const float*)d_in[5];   // (512,512)
    float* out = (float*)d_out;                // (64,512,512)

    cudaFuncSetAttribute(k3_kernel, cudaFuncAttributeMaxDynamicSharedMemorySize, K3_SMEM);

    k1_kernel<<<Bb * Nn, 288>>>(x, W1, W2, W3);
    kvs_kernel<<<(Nn * Nn) / 256, 256>>>(Vs);
    k2_kernel<<<dim3(Nn / 128, Nn / 8, Bb), 256>>>(bs);
    k3_kernel<<<dim3(Nn / 128, Nn / 128, Bb), 256, K3_SMEM>>>(out);
    k4_kernel<<<dim3(Nn / 32, Bb), 256>>>(out);
}

// round 4
// speedup vs baseline: 1.7948x; 1.0279x over previous
#include <cuda_runtime.h>
#include <cuda_bf16.h>
#include <cstdint>

#define Bb 64
#define Nn 512
#define Ff 16
#define Tt 288

// ---------------- scratch (static device globals; no allocs) ----------------
__device__ float g_y [Bb * Nn * Ff];
__device__ float g_zz[Bb * Nn * Ff];
__device__ __nv_bfloat16 g_sg_hi[(size_t)Bb * Nn * Nn];
__device__ __nv_bfloat16 g_sg_lo[(size_t)Bb * Nn * Nn];
__device__ __nv_bfloat16 g_vs_hi[Nn * Nn];
__device__ __nv_bfloat16 g_vs_lo[Nn * Nn];

// ------------------------------- PTX helpers --------------------------------
__device__ __forceinline__ uint32_t smem_u32(const void* p) {
    uint32_t a;
    asm("{ .reg .u64 t; cvta.to.shared.u64 t, %1; cvt.u32.u64 %0, t; }" : "=r"(a) : "l"(p));
    return a;
}
__device__ __forceinline__ void cp16(uint32_t dst, const void* src) {
    asm volatile("cp.async.cg.shared.global [%0], [%1], 16;" :: "r"(dst), "l"(src) : "memory");
}
__device__ __forceinline__ void ldm_x4(uint32_t* r, uint32_t addr) {
    asm volatile("ldmatrix.sync.aligned.m8n8.x4.shared.b16 {%0,%1,%2,%3}, [%4];"
                 : "=r"(r[0]), "=r"(r[1]), "=r"(r[2]), "=r"(r[3]) : "r"(addr));
}
__device__ __forceinline__ void mma16816(float* d, const uint32_t* a, const uint32_t* bb) {
    asm volatile(
        "mma.sync.aligned.m16n8k16.row.col.f32.bf16.bf16.f32 "
        "{%0,%1,%2,%3}, {%4,%5,%6,%7}, {%8,%9}, {%0,%1,%2,%3};"
        : "+f"(d[0]), "+f"(d[1]), "+f"(d[2]), "+f"(d[3])
        : "r"(a[0]), "r"(a[1]), "r"(a[2]), "r"(a[3]), "r"(bb[0]), "r"(bb[1]));
}

// ---------------------------------------------------------------------------
// K1: per (b,n) block, 288 threads: y, zz from x (rank-16 factorization).
// ---------------------------------------------------------------------------
__global__ __launch_bounds__(288) void k1_kernel(const float* __restrict__ x,
                                                 const float* __restrict__ W1,
                                                 const float* __restrict__ W2,
                                                 const float* __restrict__ W3) {
    __shared__ float xs[Ff * Tt];
    __shared__ float rs[Tt];
    __shared__ float w1s[Tt];
    __shared__ float w3s[Ff];
    __shared__ float red[Ff];

    const int tid = threadIdx.x;
    const int bn  = blockIdx.x;

    const float4* xp4 = reinterpret_cast<const float4*>(x + (size_t)bn * (Ff * Tt));
    float4* xs4 = reinterpret_cast<float4*>(xs);
#pragma unroll
    for (int i = 0; i < 4; i++) xs4[tid + Tt * i] = xp4[tid + Tt * i];
    w1s[tid] = W1[tid];
    if (tid < Ff) w3s[tid] = W3[tid];
    __syncthreads();

    float r = 0.f;
#pragma unroll
    for (int f = 0; f < Ff; f++) r += xs[f * Tt + tid] * w3s[f];
    rs[tid] = r;

    const int w = tid >> 5, l = tid & 31;

    for (int f = w; f < Ff; f += 9) {
        float p = 0.f;
#pragma unroll
        for (int c = 0; c < 9; c++) p += xs[f * Tt + l + 32 * c] * w1s[l + 32 * c];
#pragma unroll
        for (int o = 16; o > 0; o >>= 1) p += __shfl_down_sync(0xffffffffu, p, o);
        if (l == 0) red[f] = p;
    }
    __syncthreads();

    if (tid < Ff) g_y[(size_t)bn * Ff + tid] = red[tid];

    for (int f = w; f < Ff; f += 9) {
        float p = 0.f;
#pragma unroll
        for (int c = 0; c < 9; c++) p += W2[f * Tt + l + 32 * c] * rs[l + 32 * c];
#pragma unroll
        for (int o = 16; o > 0; o >>= 1) p += __shfl_down_sync(0xffffffffu, p, o);
        if (l == 0) g_zz[(size_t)bn * Ff + f] = p;
    }
}

// ---------------------------------------------------------------------------
// KVS: split V_s (512x512 fp32) into bf16 hi/lo.
// ---------------------------------------------------------------------------
__global__ __launch_bounds__(256) void kvs_kernel(const float* __restrict__ Vs) {
    int i = blockIdx.x * 256 + threadIdx.x;
    float v = Vs[i];
    __nv_bfloat16 hi = __float2bfloat16(v);
    __nv_bfloat16 lo = __float2bfloat16(v - __bfloat162float(hi));
    g_vs_hi[i] = hi;
    g_vs_lo[i] = lo;
}

// ---------------------------------------------------------------------------
// K2: Sg = sigmoid(y . zz + b_s), written as bf16 hi/lo split.
// ---------------------------------------------------------------------------
__global__ __launch_bounds__(256) void k2_kernel(const float* __restrict__ bs) {
    __shared__ float ys[8][Ff];
    __shared__ float zs[Ff][132];

    const int tid = threadIdx.x;
    const int m0  = blockIdx.x * 128;
    const int n0  = blockIdx.y * 8;
    const int b   = blockIdx.z;

    if (tid < 128)
        ys[tid >> 4][tid & 15] = g_y[((size_t)b * Nn + n0) * Ff + tid];

    const float4* zz4 = reinterpret_cast<const float4*>(g_zz + ((size_t)b * Nn + m0) * Ff);
#pragma unroll
    for (int i = 0; i < 2; i++) {
        int q = tid + 256 * i;
        int m = q >> 2, fq = q & 3;
        float4 v = zz4[q];
        zs[fq * 4 + 0][m] = v.x;
        zs[fq * 4 + 1][m] = v.y;
        zs[fq * 4 + 2][m] = v.z;
        zs[fq * 4 + 3][m] = v.w;
    }
    __syncthreads();

    const int m4 = tid & 31, nq = tid >> 5;
    float4 acc = *reinterpret_cast<const float4*>(bs + (size_t)(n0 + nq) * Nn + m0 + m4 * 4);
#pragma unroll
    for (int f = 0; f < Ff; f++) {
        float yf = ys[nq][f];
        float4 z = *reinterpret_cast<const float4*>(&zs[f][m4 * 4]);
        acc.x += yf * z.x;
        acc.y += yf * z.y;
        acc.z += yf * z.z;
        acc.w += yf * z.w;
    }
    acc.x = 1.f / (1.f + __expf(-acc.x));
    acc.y = 1.f / (1.f + __expf(-acc.y));
    acc.z = 1.f / (1.f + __expf(-acc.z));
    acc.w = 1.f / (1.f + __expf(-acc.w));

    __nv_bfloat16 h0 = __float2bfloat16(acc.x);
    __nv_bfloat16 h1 = __float2bfloat16(acc.y);
    __nv_bfloat16 h2 = __float2bfloat16(acc.z);
    __nv_bfloat16 h3 = __float2bfloat16(acc.w);
    __nv_bfloat16 l0 = __float2bfloat16(acc.x - __bfloat162float(h0));
    __nv_bfloat16 l1 = __float2bfloat16(acc.y - __bfloat162float(h1));
    __nv_bfloat16 l2 = __float2bfloat16(acc.z - __bfloat162float(h2));
    __nv_bfloat16 l3 = __float2bfloat16(acc.w - __bfloat162float(h3));

    size_t base = ((size_t)b * Nn + n0 + nq) * Nn + m0;
    __nv_bfloat162* dh = reinterpret_cast<__nv_bfloat162*>(g_sg_hi + base) + m4 * 2;
    __nv_bfloat162* dl = reinterpret_cast<__nv_bfloat162*>(g_sg_lo + base) + m4 * 2;
    dh[0] = __halves2bfloat162(h0, h1);
    dh[1] = __halves2bfloat162(h2, h3);
    dl[0] = __halves2bfloat162(l0, l1);
    dl[1] = __halves2bfloat162(l2, l3);
}

// ---------------------------------------------------------------------------
// K3: s[b] = Sg[b] @ V_s^T via mma.sync bf16 (3-way split, fp32 accumulate).
//   128x128 tile / CTA, 8 warps (2x4), K chunks of 64.
//   3-stage cp.async pipeline, ONE sync per chunk, fragment-reuse pass order,
//   B loaded with ldmatrix.x4 (2 n-tiles per instr).
// ---------------------------------------------------------------------------
#define K3_STRIDE 144                      // bytes per smem row (64 bf16 + 8 pad)
#define K3_ARR    (128 * K3_STRIDE)        // 18432 B per array
#define K3_A_HI   0
#define K3_A_LO   (1 * K3_ARR)
#define K3_B_HI   (2 * K3_ARR)
#define K3_B_LO   (3 * K3_ARR)
#define K3_STAGE  (4 * K3_ARR)             // 73728 B
#define K3_SMEM   (3 * K3_STAGE)           // 221184 B

extern __shared__ char k3_smem[];

__global__ void __launch_bounds__(256, 1) k3_kernel(float* __restrict__ out) {
    const int tid  = threadIdx.x;
    const int wid  = tid >> 5;
    const int lane = tid & 31;
    const int i0   = blockIdx.x * 128;
    const int n0   = blockIdx.y * 128;
    const int b    = blockIdx.z;

    const uint32_t sbase = smem_u32(k3_smem);

    const __nv_bfloat16* Ahi = g_sg_hi + ((size_t)b * Nn + n0) * Nn;
    const __nv_bfloat16* Alo = g_sg_lo + ((size_t)b * Nn + n0) * Nn;
    const __nv_bfloat16* Bhi = g_vs_hi + (size_t)i0 * Nn;
    const __nv_bfloat16* Blo = g_vs_lo + (size_t)i0 * Nn;

    const int wr = wid >> 2;   // 0..1 : row half (64 rows)
    const int wc = wid & 3;    // 0..3 : col quarter (32 cols)

    // A ldmatrix.x4 lane offset: matrices (m0-7,k0),(m8-15,k0),(m0-7,k8),(m8-15,k8)
    const int am = lane >> 3;
    const uint32_t aoff = (uint32_t)(((am & 1) * 8 + (lane & 7)) * K3_STRIDE + (am >> 1) * 16)
                        + (uint32_t)(wr * 64 * K3_STRIDE);
    // B ldmatrix.x4 lane offset: matrices (n0-7,k0),(n0-7,k8),(n8-15,k0),(n8-15,k8)
    const int bg = lane >> 3;
    const uint32_t boff = (uint32_t)(((bg >> 1) * 8 + (lane & 7)) * K3_STRIDE + (bg & 1) * 16)
                        + (uint32_t)(wc * 32 * K3_STRIDE);

    float acc[4][4][4];
#pragma unroll
    for (int mi = 0; mi < 4; mi++)
#pragma unroll
        for (int ni = 0; ni < 4; ni++)
#pragma unroll
            for (int q = 0; q < 4; q++) acc[mi][ni][q] = 0.f;

#define K3_LOAD(CHUNK, STAGE)                                                      \
    do {                                                                           \
        const int k0_ = (CHUNK) * 64;                                              \
        const uint32_t st_ = sbase + (STAGE) * K3_STAGE;                           \
        _Pragma("unroll")                                                          \
        for (int i_ = 0; i_ < 4; i_++) {                                           \
            int idx_ = tid + 256 * i_;                                             \
            int row_ = idx_ >> 3, cc_ = idx_ & 7;                                  \
            uint32_t so_ = (uint32_t)(row_ * K3_STRIDE + cc_ * 16);                \
            size_t go_ = (size_t)row_ * Nn + k0_ + cc_ * 8;                        \
            cp16(st_ + K3_A_HI + so_, Ahi + go_);                                  \
            cp16(st_ + K3_A_LO + so_, Alo + go_);                                  \
            cp16(st_ + K3_B_HI + so_, Bhi + go_);                                  \
            cp16(st_ + K3_B_LO + so_, Blo + go_);                                  \
        }                                                                          \
        asm volatile("cp.async.commit_group;" ::: "memory");                       \
    } while (0)

    K3_LOAD(0, 0);
    K3_LOAD(1, 1);

    for (int c = 0; c < 8; c++) {
        if (c < 7) {
            asm volatile("cp.async.wait_group 1;" ::: "memory");
        } else {
            asm volatile("cp.async.wait_group 0;" ::: "memory");
        }
        __syncthreads();

        if (c + 2 < 8) K3_LOAD(c + 2, (c + 2) % 3);

        const uint32_t st = sbase + (c % 3) * K3_STAGE;
        const uint32_t Ahb = st + K3_A_HI + aoff;
        const uint32_t Alb = st + K3_A_LO + aoff;
        const uint32_t Bhb = st + K3_B_HI + boff;
        const uint32_t Blb = st + K3_B_LO + boff;

#pragma unroll
        for (int ks = 0; ks < 4; ks++) {
            const uint32_t kso = (uint32_t)(ks * 32);

            uint32_t ah[4][4];
#pragma unroll
            for (int mi = 0; mi < 4; mi++)
                ldm_x4(ah[mi], Ahb + (uint32_t)(mi * 16 * K3_STRIDE) + kso);

            uint32_t bh[4][2];
#pragma unroll
            for (int dn = 0; dn < 2; dn++) {
                uint32_t r[4];
                ldm_x4(r, Bhb + (uint32_t)(dn * 16 * K3_STRIDE) + kso);
                bh[2 * dn][0] = r[0]; bh[2 * dn][1] = r[1];
                bh[2 * dn + 1][0] = r[2]; bh[2 * dn + 1][1] = r[3];
            }

            // pass 1: hi * hi
#pragma unroll
            for (int mi = 0; mi < 4; mi++)
#pragma unroll
                for (int ni = 0; ni < 4; ni++)
                    mma16816(acc[mi][ni], ah[mi], bh[ni]);

            // pass 2: hi * lo  (reuse ah)
            {
                uint32_t bl[4][2];
#pragma unroll
                for (int dn = 0; dn < 2; dn++) {
                    uint32_t r[4];
                    ldm_x4(r, Blb + (uint32_t)(dn * 16 * K3_STRIDE) + kso);
                    bl[2 * dn][0] = r[0]; bl[2 * dn][1] = r[1];
                    bl[2 * dn + 1][0] = r[2]; bl[2 * dn + 1][1] = r[3];
                }
#pragma unroll
                for (int mi = 0; mi < 4; mi++)
#pragma unroll
                    for (int ni = 0; ni < 4; ni++)
                        mma16816(acc[mi][ni], ah[mi], bl[ni]);
            }

            // pass 3: lo * hi  (reuse bh)
            {
                uint32_t al[4][4];
#pragma unroll
                for (int mi = 0; mi < 4; mi++)
                    ldm_x4(al[mi], Alb + (uint32_t)(mi * 16 * K3_STRIDE) + kso);
#pragma unroll
                for (int mi = 0; mi < 4; mi++)
#pragma unroll
                    for (int ni = 0; ni < 4; ni++)
                        mma16816(acc[mi][ni], al[mi], bh[ni]);
            }
        }
    }
#undef K3_LOAD

    // epilogue: m16n8 fragment layout -> global
    const int rr = lane >> 2;
    const int cc = (lane & 3) * 2;
#pragma unroll
    for (int mi = 0; mi < 4; mi++) {
#pragma unroll
        for (int ni = 0; ni < 4; ni++) {
            int row = n0 + wr * 64 + mi * 16 + rr;
            int col = i0 + wc * 32 + ni * 8 + cc;
            float* p0 = out + ((size_t)b * Nn + row) * Nn + col;
            float* p1 = out + ((size_t)b * Nn + row + 8) * Nn + col;
            *reinterpret_cast<float2*>(p0) = make_float2(acc[mi][ni][0], acc[mi][ni][1]);
            *reinterpret_cast<float2*>(p1) = make_float2(acc[mi][ni][2], acc[mi][ni][3]);
        }
    }
}

// ---------------------------------------------------------------------------
// K4: in-place softmax over axis 1 (n) of d_out[b,n,i].
// ---------------------------------------------------------------------------
__global__ __launch_bounds__(256) void k4_kernel(float* __restrict__ out) {
    const int tid = threadIdx.x;
    const int col = tid & 31, seg = tid >> 5;
    const int i0  = blockIdx.x * 32;
    const int b   = blockIdx.y;

    float* base = out + (size_t)b * Nn * Nn + i0 + col;

    float m = -1e30f, s = 0.f;
    for (int n = seg * 64; n < seg * 64 + 64; n++) {
        float v  = base[(size_t)n * Nn];
        float mn = fmaxf(m, v);
        s = s * __expf(m - mn) + __expf(v - mn);
        m = mn;
    }

    __shared__ float sm[8][32], ssum[8][32];
    sm[seg][col]   = m;
    ssum[seg][col] = s;
    __syncthreads();

    float M = -1e30f;
#pragma unroll
    for (int g = 0; g < 8; g++) M = fmaxf(M, sm[g][col]);
    float S = 0.f;
#pragma unroll
    for (int g = 0; g < 8; g++) S += ssum[g][col] * __expf(sm[g][col] - M);
    float invS = 1.f / S;

    for (int n = seg * 64; n < seg * 64 + 64; n++) {
        float v = base[(size_t)n * Nn];
        base[(size_t)n * Nn] = __expf(v - M) * invS;
    }
}

// ---------------------------------------------------------------------------
extern "C" void kernel_launch(void* const* d_in, const int* in_sizes, int n_in,
                              void* d_out, int out_size) {
    const float* x  = (const float*)d_in[0];   // (64,512,16,288)
    const float* W1 = (const float*)d_in[1];   // (288,)
    const float* W2 = (const float*)d_in[2];   // (16,288)
    const float* W3 = (const float*)d_in[3];   // (16,)
    const float* bs = (const float*)d_in[4];   // (1,512,512)
    const float* Vs = (const float*)d_in[5];   // (512,512)
    float* out = (float*)d_out;                // (64,512,512)

    cudaFuncSetAttribute(k3_kernel, cudaFuncAttributeMaxDynamicSharedMemorySize, K3_SMEM);

    k1_kernel<<<Bb * Nn, 288>>>(x, W1, W2, W3);
    kvs_kernel<<<(Nn * Nn) / 256, 256>>>(Vs);
    k2_kernel<<<dim3(Nn / 128, Nn / 8, Bb), 256>>>(bs);
    k3_kernel<<<dim3(Nn / 128, Nn / 128, Bb), 256, K3_SMEM>>>(out);
    k4_kernel<<<dim3(Nn / 32, Bb), 256>>>(out);
}

// round 5
// speedup vs baseline: 2.1177x; 1.1799x over previous
#include <cuda_runtime.h>
#include <cuda_fp16.h>
#include <cstdint>

#define Bb 64
#define Nn 512
#define Ff 16
#define Tt 288

// ---------------- scratch (static device globals; no allocs) ----------------
__device__ float g_y [Bb * Nn * Ff];
__device__ float g_zz[Bb * Nn * Ff];
__device__ __half g_sg_hi[(size_t)Bb * Nn * Nn];
__device__ __half g_sg_lo[(size_t)Bb * Nn * Nn];
__device__ __half g_vs_hi[Nn * Nn];

// ------------------------------- PTX helpers --------------------------------
__device__ __forceinline__ uint32_t smem_u32(const void* p) {
    uint32_t a;
    asm("{ .reg .u64 t; cvta.to.shared.u64 t, %1; cvt.u32.u64 %0, t; }" : "=r"(a) : "l"(p));
    return a;
}
__device__ __forceinline__ void cp16(uint32_t dst, const void* src) {
    asm volatile("cp.async.cg.shared.global [%0], [%1], 16;" :: "r"(dst), "l"(src) : "memory");
}
__device__ __forceinline__ void ldm_x4(uint32_t* r, uint32_t addr) {
    asm volatile("ldmatrix.sync.aligned.m8n8.x4.shared.b16 {%0,%1,%2,%3}, [%4];"
                 : "=r"(r[0]), "=r"(r[1]), "=r"(r[2]), "=r"(r[3]) : "r"(addr));
}
__device__ __forceinline__ void mma16816(float* d, const uint32_t* a, const uint32_t* bb) {
    asm volatile(
        "mma.sync.aligned.m16n8k16.row.col.f32.f16.f16.f32 "
        "{%0,%1,%2,%3}, {%4,%5,%6,%7}, {%8,%9}, {%0,%1,%2,%3};"
        : "+f"(d[0]), "+f"(d[1]), "+f"(d[2]), "+f"(d[3])
        : "r"(a[0]), "r"(a[1]), "r"(a[2]), "r"(a[3]), "r"(bb[0]), "r"(bb[1]));
}

// ---------------------------------------------------------------------------
// K1: per (b,n) block, 288 threads: y, zz from x (rank-16 factorization).
// ---------------------------------------------------------------------------
__global__ __launch_bounds__(288) void k1_kernel(const float* __restrict__ x,
                                                 const float* __restrict__ W1,
                                                 const float* __restrict__ W2,
                                                 const float* __restrict__ W3) {
    __shared__ float xs[Ff * Tt];
    __shared__ float rs[Tt];
    __shared__ float w1s[Tt];
    __shared__ float w3s[Ff];
    __shared__ float red[Ff];

    const int tid = threadIdx.x;
    const int bn  = blockIdx.x;

    const float4* xp4 = reinterpret_cast<const float4*>(x + (size_t)bn * (Ff * Tt));
    float4* xs4 = reinterpret_cast<float4*>(xs);
#pragma unroll
    for (int i = 0; i < 4; i++) xs4[tid + Tt * i] = xp4[tid + Tt * i];
    w1s[tid] = W1[tid];
    if (tid < Ff) w3s[tid] = W3[tid];
    __syncthreads();

    float r = 0.f;
#pragma unroll
    for (int f = 0; f < Ff; f++) r += xs[f * Tt + tid] * w3s[f];
    rs[tid] = r;

    const int w = tid >> 5, l = tid & 31;

    for (int f = w; f < Ff; f += 9) {
        float p = 0.f;
#pragma unroll
        for (int c = 0; c < 9; c++) p += xs[f * Tt + l + 32 * c] * w1s[l + 32 * c];
#pragma unroll
        for (int o = 16; o > 0; o >>= 1) p += __shfl_down_sync(0xffffffffu, p, o);
        if (l == 0) red[f] = p;
    }
    __syncthreads();

    if (tid < Ff) g_y[(size_t)bn * Ff + tid] = red[tid];

    for (int f = w; f < Ff; f += 9) {
        float p = 0.f;
#pragma unroll
        for (int c = 0; c < 9; c++) p += W2[f * Tt + l + 32 * c] * rs[l + 32 * c];
#pragma unroll
        for (int o = 16; o > 0; o >>= 1) p += __shfl_down_sync(0xffffffffu, p, o);
        if (l == 0) g_zz[(size_t)bn * Ff + f] = p;
    }
}

// ---------------------------------------------------------------------------
// KVS: V_s (512x512 fp32) -> fp16 hi.
// ---------------------------------------------------------------------------
__global__ __launch_bounds__(256) void kvs_kernel(const float* __restrict__ Vs) {
    int i = blockIdx.x * 256 + threadIdx.x;
    g_vs_hi[i] = __float2half_rn(Vs[i]);
}

// ---------------------------------------------------------------------------
// K2: Sg = sigmoid(y . zz + b_s), written as fp16 hi/lo split.
// ---------------------------------------------------------------------------
__global__ __launch_bounds__(256) void k2_kernel(const float* __restrict__ bs) {
    __shared__ float ys[8][Ff];
    __shared__ float zs[Ff][132];

    const int tid = threadIdx.x;
    const int m0  = blockIdx.x * 128;
    const int n0  = blockIdx.y * 8;
    const int b   = blockIdx.z;

    if (tid < 128)
        ys[tid >> 4][tid & 15] = g_y[((size_t)b * Nn + n0) * Ff + tid];

    const float4* zz4 = reinterpret_cast<const float4*>(g_zz + ((size_t)b * Nn + m0) * Ff);
#pragma unroll
    for (int i = 0; i < 2; i++) {
        int q = tid + 256 * i;
        int m = q >> 2, fq = q & 3;
        float4 v = zz4[q];
        zs[fq * 4 + 0][m] = v.x;
        zs[fq * 4 + 1][m] = v.y;
        zs[fq * 4 + 2][m] = v.z;
        zs[fq * 4 + 3][m] = v.w;
    }
    __syncthreads();

    const int m4 = tid & 31, nq = tid >> 5;
    float4 acc = *reinterpret_cast<const float4*>(bs + (size_t)(n0 + nq) * Nn + m0 + m4 * 4);
#pragma unroll
    for (int f = 0; f < Ff; f++) {
        float yf = ys[nq][f];
        float4 z = *reinterpret_cast<const float4*>(&zs[f][m4 * 4]);
        acc.x += yf * z.x;
        acc.y += yf * z.y;
        acc.z += yf * z.z;
        acc.w += yf * z.w;
    }
    acc.x = 1.f / (1.f + __expf(-acc.x));
    acc.y = 1.f / (1.f + __expf(-acc.y));
    acc.z = 1.f / (1.f + __expf(-acc.z));
    acc.w = 1.f / (1.f + __expf(-acc.w));

    __half h0 = __float2half_rn(acc.x);
    __half h1 = __float2half_rn(acc.y);
    __half h2 = __float2half_rn(acc.z);
    __half h3 = __float2half_rn(acc.w);
    __half l0 = __float2half_rn(acc.x - __half2float(h0));
    __half l1 = __float2half_rn(acc.y - __half2float(h1));
    __half l2 = __float2half_rn(acc.z - __half2float(h2));
    __half l3 = __float2half_rn(acc.w - __half2float(h3));

    size_t base = ((size_t)b * Nn + n0 + nq) * Nn + m0;
    __half2* dh = reinterpret_cast<__half2*>(g_sg_hi + base) + m4 * 2;
    __half2* dl = reinterpret_cast<__half2*>(g_sg_lo + base) + m4 * 2;
    dh[0] = __halves2half2(h0, h1);
    dh[1] = __halves2half2(h2, h3);
    dl[0] = __halves2half2(l0, l1);
    dl[1] = __halves2half2(l2, l3);
}

// ---------------------------------------------------------------------------
// K3: s[b] = Sg[b] @ V_s^T via mma.sync fp16 (2-pass hi/lo, fp32 accumulate).
//   128x128 tile / CTA, 8 warps (2x4), K chunks of 64, double buffer,
//   2 CTAs/SM (smem 110592 B, <=128 regs).
// ---------------------------------------------------------------------------
#define K3_STRIDE 144                      // bytes per smem row (64 fp16 + pad)
#define K3_ARR    (128 * K3_STRIDE)        // 18432 B per array
#define K3_A_HI   0
#define K3_A_LO   (1 * K3_ARR)
#define K3_B_HI   (2 * K3_ARR)
#define K3_STAGE  (3 * K3_ARR)             // 55296 B
#define K3_SMEM   (2 * K3_STAGE)           // 110592 B

extern __shared__ char k3_smem[];

__global__ void __launch_bounds__(256, 2) k3_kernel(float* __restrict__ out) {
    const int tid  = threadIdx.x;
    const int wid  = tid >> 5;
    const int lane = tid & 31;
    const int i0   = blockIdx.x * 128;
    const int n0   = blockIdx.y * 128;
    const int b    = blockIdx.z;

    const uint32_t sbase = smem_u32(k3_smem);

    const __half* Ahi = g_sg_hi + ((size_t)b * Nn + n0) * Nn;
    const __half* Alo = g_sg_lo + ((size_t)b * Nn + n0) * Nn;
    const __half* Bhi = g_vs_hi + (size_t)i0 * Nn;

    const int wr = wid >> 2;   // 0..1 : row half (64 rows)
    const int wc = wid & 3;    // 0..3 : col quarter (32 cols)

    // A ldmatrix.x4 lane offset: matrices (m0-7,k0),(m8-15,k0),(m0-7,k8),(m8-15,k8)
    const int am = lane >> 3;
    const uint32_t aoff = (uint32_t)(((am & 1) * 8 + (lane & 7)) * K3_STRIDE + (am >> 1) * 16)
                        + (uint32_t)(wr * 64 * K3_STRIDE);
    // B ldmatrix.x4 lane offset: matrices (n0-7,k0),(n0-7,k8),(n8-15,k0),(n8-15,k8)
    const int bg = lane >> 3;
    const uint32_t boff = (uint32_t)(((bg >> 1) * 8 + (lane & 7)) * K3_STRIDE + (bg & 1) * 16)
                        + (uint32_t)(wc * 32 * K3_STRIDE);

    float acc[4][4][4];
#pragma unroll
    for (int mi = 0; mi < 4; mi++)
#pragma unroll
        for (int ni = 0; ni < 4; ni++)
#pragma unroll
            for (int q = 0; q < 4; q++) acc[mi][ni][q] = 0.f;

#define K3_LOAD(CHUNK, STAGE)                                                      \
    do {                                                                           \
        const int k0_ = (CHUNK) * 64;                                              \
        const uint32_t st_ = sbase + (STAGE) * K3_STAGE;                           \
        _Pragma("unroll")                                                          \
        for (int i_ = 0; i_ < 4; i_++) {                                           \
            int idx_ = tid + 256 * i_;                                             \
            int row_ = idx_ >> 3, cc_ = idx_ & 7;                                  \
            uint32_t so_ = (uint32_t)(row_ * K3_STRIDE + cc_ * 16);                \
            size_t go_ = (size_t)row_ * Nn + k0_ + cc_ * 8;                        \
            cp16(st_ + K3_A_HI + so_, Ahi + go_);                                  \
            cp16(st_ + K3_A_LO + so_, Alo + go_);                                  \
            cp16(st_ + K3_B_HI + so_, Bhi + go_);                                  \
        }                                                                          \
        asm volatile("cp.async.commit_group;" ::: "memory");                       \
    } while (0)

    K3_LOAD(0, 0);

    for (int c = 0; c < 8; c++) {
        if (c + 1 < 8) {
            K3_LOAD(c + 1, (c + 1) & 1);
            asm volatile("cp.async.wait_group 1;" ::: "memory");
        } else {
            asm volatile("cp.async.wait_group 0;" ::: "memory");
        }
        __syncthreads();

        const uint32_t st = sbase + (c & 1) * K3_STAGE;
        const uint32_t Ahb = st + K3_A_HI + aoff;
        const uint32_t Alb = st + K3_A_LO + aoff;
        const uint32_t Bhb = st + K3_B_HI + boff;

#pragma unroll
        for (int ks = 0; ks < 4; ks++) {
            const uint32_t kso = (uint32_t)(ks * 32);

            uint32_t ah[4][4];
#pragma unroll
            for (int mi = 0; mi < 4; mi++)
                ldm_x4(ah[mi], Ahb + (uint32_t)(mi * 16 * K3_STRIDE) + kso);

            uint32_t bh[4][2];
#pragma unroll
            for (int dn = 0; dn < 2; dn++) {
                uint32_t r[4];
                ldm_x4(r, Bhb + (uint32_t)(dn * 16 * K3_STRIDE) + kso);
                bh[2 * dn][0] = r[0]; bh[2 * dn][1] = r[1];
                bh[2 * dn + 1][0] = r[2]; bh[2 * dn + 1][1] = r[3];
            }

            // pass 1: hi * hi
#pragma unroll
            for (int mi = 0; mi < 4; mi++)
#pragma unroll
                for (int ni = 0; ni < 4; ni++)
                    mma16816(acc[mi][ni], ah[mi], bh[ni]);

            // pass 2: lo * hi (reuse bh)
            {
                uint32_t al[4][4];
#pragma unroll
                for (int mi = 0; mi < 4; mi++)
                    ldm_x4(al[mi], Alb + (uint32_t)(mi * 16 * K3_STRIDE) + kso);
#pragma unroll
                for (int mi = 0; mi < 4; mi++)
#pragma unroll
                    for (int ni = 0; ni < 4; ni++)
                        mma16816(acc[mi][ni], al[mi], bh[ni]);
            }
        }
        __syncthreads();
    }
#undef K3_LOAD

    // epilogue: m16n8 fragment layout -> global
    const int rr = lane >> 2;
    const int cc = (lane & 3) * 2;
#pragma unroll
    for (int mi = 0; mi < 4; mi++) {
#pragma unroll
        for (int ni = 0; ni < 4; ni++) {
            int row = n0 + wr * 64 + mi * 16 + rr;
            int col = i0 + wc * 32 + ni * 8 + cc;
            float* p0 = out + ((size_t)b * Nn + row) * Nn + col;
            float* p1 = out + ((size_t)b * Nn + row + 8) * Nn + col;
            *reinterpret_cast<float2*>(p0) = make_float2(acc[mi][ni][0], acc[mi][ni][1]);
            *reinterpret_cast<float2*>(p1) = make_float2(acc[mi][ni][2], acc[mi][ni][3]);
        }
    }
}

// ---------------------------------------------------------------------------
// K4: in-place softmax over axis 1 (n) of d_out[b,n,i].
// ---------------------------------------------------------------------------
__global__ __launch_bounds__(256) void k4_kernel(float* __restrict__ out) {
    const int tid = threadIdx.x;
    const int col = tid & 31, seg = tid >> 5;
    const int i0  = blockIdx.x * 32;
    const int b   = blockIdx.y;

    float* base = out + (size_t)b * Nn * Nn + i0 + col;

    float m = -1e30f, s = 0.f;
    for (int n = seg * 64; n < seg * 64 + 64; n++) {
        float v  = base[(size_t)n * Nn];
        float mn = fmaxf(m, v);
        s = s * __expf(m - mn) + __expf(v - mn);
        m = mn;
    }

    __shared__ float sm[8][32], ssum[8][32];
    sm[seg][col]   = m;
    ssum[seg][col] = s;
    __syncthreads();

    float M = -1e30f;
#pragma unroll
    for (int g = 0; g < 8; g++) M = fmaxf(M, sm[g][col]);
    float S = 0.f;
#pragma unroll
    for (int g = 0; g < 8; g++) S += ssum[g][col] * __expf(sm[g][col] - M);
    float invS = 1.f / S;

    for (int n = seg * 64; n < seg * 64 + 64; n++) {
        float v = base[(size_t)n * Nn];
        base[(size_t)n * Nn] = __expf(v - M) * invS;
    }
}

// ---------------------------------------------------------------------------
extern "C" void kernel_launch(void* const* d_in, const int* in_sizes, int n_in,
                              void* d_out, int out_size) {
    const float* x  = (const float*)d_in[0];   // (64,512,16,288)
    const float* W1 = (const float*)d_in[1];   // (288,)
    const float* W2 = (const float*)d_in[2];   // (16,288)
    const float* W3 = (const float*)d_in[3];   // (16,)
    const float* bs = (const float*)d_in[4];   // (1,512,512)
    const float* Vs = (const float*)d_in[5];   // (512,512)
    float* out = (float*)d_out;                // (64,512,512)

    cudaFuncSetAttribute(k3_kernel, cudaFuncAttributeMaxDynamicSharedMemorySize, K3_SMEM);

    k1_kernel<<<Bb * Nn, 288>>>(x, W1, W2, W3);
    kvs_kernel<<<(Nn * Nn) / 256, 256>>>(Vs);
    k2_kernel<<<dim3(Nn / 128, Nn / 8, Bb), 256>>>(bs);
    k3_kernel<<<dim3(Nn / 128, Nn / 128, Bb), 256, K3_SMEM>>>(out);
    k4_kernel<<<dim3(Nn / 32, Bb), 256>>>(out);
}

// round 6
// speedup vs baseline: 2.4358x; 1.1502x over previous
#include <cuda_runtime.h>
#include <cuda_fp16.h>
#include <cstdint>

#define Bb 64
#define Nn 512
#define Ff 16
#define Tt 288

// ---------------- scratch (static device globals; no allocs) ----------------
__device__ float g_y [Bb * Nn * Ff];
__device__ float g_zz[Bb * Nn * Ff];
__device__ __half g_sg_u[(size_t)Bb * Nn * Nn];   // sigmoid(..) - 0.5, fp16
__device__ __half g_vs_hi[Nn * Nn];
__device__ float  g_vsum[Nn];                     // rowsum of V_s (fp32, exact)

// ------------------------------- PTX helpers --------------------------------
__device__ __forceinline__ uint32_t smem_u32(const void* p) {
    uint32_t a;
    asm("{ .reg .u64 t; cvta.to.shared.u64 t, %1; cvt.u32.u64 %0, t; }" : "=r"(a) : "l"(p));
    return a;
}
__device__ __forceinline__ void cp16(uint32_t dst, const void* src) {
    asm volatile("cp.async.cg.shared.global [%0], [%1], 16;" :: "r"(dst), "l"(src) : "memory");
}
__device__ __forceinline__ void ldm_x4(uint32_t* r, uint32_t addr) {
    asm volatile("ldmatrix.sync.aligned.m8n8.x4.shared.b16 {%0,%1,%2,%3}, [%4];"
                 : "=r"(r[0]), "=r"(r[1]), "=r"(r[2]), "=r"(r[3]) : "r"(addr));
}
__device__ __forceinline__ void mma16816(float* d, const uint32_t* a, const uint32_t* bb) {
    asm volatile(
        "mma.sync.aligned.m16n8k16.row.col.f32.f16.f16.f32 "
        "{%0,%1,%2,%3}, {%4,%5,%6,%7}, {%8,%9}, {%0,%1,%2,%3};"
        : "+f"(d[0]), "+f"(d[1]), "+f"(d[2]), "+f"(d[3])
        : "r"(a[0]), "r"(a[1]), "r"(a[2]), "r"(a[3]), "r"(bb[0]), "r"(bb[1]));
}

// ---------------------------------------------------------------------------
// K1: 2 bn per block, cp.async pipelined. 288 threads.
// ---------------------------------------------------------------------------
__global__ __launch_bounds__(288) void k1_kernel(const float* __restrict__ x,
                                                 const float* __restrict__ W1,
                                                 const float* __restrict__ W2,
                                                 const float* __restrict__ W3) {
    __shared__ float xs[2][Ff * Tt];
    __shared__ float rs[Tt];
    __shared__ float w1s[Tt];
    __shared__ float w3s[Ff];
    __shared__ float red[Ff];

    const int tid = threadIdx.x;
    const int bn0 = blockIdx.x * 2;
    const uint32_t xs_addr = smem_u32(xs);

    // issue both bn loads via cp.async (4 x 16B per thread per bn)
#pragma unroll
    for (int j = 0; j < 2; j++) {
        const float* src = x + (size_t)(bn0 + j) * (Ff * Tt);
#pragma unroll
        for (int i = 0; i < 4; i++) {
            int e = tid + 288 * i;   // float4 index 0..1151
            cp16(xs_addr + (uint32_t)(j * (Ff * Tt) + e * 4) * 4u, src + e * 4);
        }
        asm volatile("cp.async.commit_group;" ::: "memory");
    }

    w1s[tid] = W1[tid];
    if (tid < Ff) w3s[tid] = W3[tid];

    const int w = tid >> 5, l = tid & 31;

#pragma unroll
    for (int j = 0; j < 2; j++) {
        if (j == 0) asm volatile("cp.async.wait_group 1;" ::: "memory");
        else        asm volatile("cp.async.wait_group 0;" ::: "memory");
        __syncthreads();

        const float* xsj = xs[j];
        const int bn = bn0 + j;

        // rs[t] = sum_f x[f][t]*W3[f]
        float r = 0.f;
#pragma unroll
        for (int f = 0; f < Ff; f++) r += xsj[f * Tt + tid] * w3s[f];
        rs[tid] = r;

        // y[f] warp reductions
        for (int f = w; f < Ff; f += 9) {
            float p0 = 0.f, p1 = 0.f, p2 = 0.f;
#pragma unroll
            for (int c = 0; c < 9; c += 3) {
                p0 += xsj[f * Tt + l + 32 * c]       * w1s[l + 32 * c];
                p1 += xsj[f * Tt + l + 32 * (c + 1)] * w1s[l + 32 * (c + 1)];
                p2 += xsj[f * Tt + l + 32 * (c + 2)] * w1s[l + 32 * (c + 2)];
            }
            float p = p0 + p1 + p2;
#pragma unroll
            for (int o = 16; o > 0; o >>= 1) p += __shfl_down_sync(0xffffffffu, p, o);
            if (l == 0) red[f] = p;
        }
        __syncthreads();

        if (tid < Ff) g_y[(size_t)bn * Ff + tid] = red[tid];

        // zz[f] warp reductions
        for (int f = w; f < Ff; f += 9) {
            float p0 = 0.f, p1 = 0.f, p2 = 0.f;
#pragma unroll
            for (int c = 0; c < 9; c += 3) {
                p0 += W2[f * Tt + l + 32 * c]       * rs[l + 32 * c];
                p1 += W2[f * Tt + l + 32 * (c + 1)] * rs[l + 32 * (c + 1)];
                p2 += W2[f * Tt + l + 32 * (c + 2)] * rs[l + 32 * (c + 2)];
            }
            float p = p0 + p1 + p2;
#pragma unroll
            for (int o = 16; o > 0; o >>= 1) p += __shfl_down_sync(0xffffffffu, p, o);
            if (l == 0) g_zz[(size_t)bn * Ff + f] = p;
        }
        // top-of-loop __syncthreads (j=1) protects rs/red reuse
    }
}

// ---------------------------------------------------------------------------
// KVS: V_s row -> fp16 + exact fp32 rowsum. One block per row (i).
// ---------------------------------------------------------------------------
__global__ __launch_bounds__(128) void kvs_kernel(const float* __restrict__ Vs) {
    __shared__ float wsum[4];
    const int row = blockIdx.x;
    const int tid = threadIdx.x;

    float4 v = reinterpret_cast<const float4*>(Vs + (size_t)row * Nn)[tid];
    __half2* dst = reinterpret_cast<__half2*>(g_vs_hi + (size_t)row * Nn) + tid * 2;
    dst[0] = __halves2half2(__float2half_rn(v.x), __float2half_rn(v.y));
    dst[1] = __halves2half2(__float2half_rn(v.z), __float2half_rn(v.w));

    float s = v.x + v.y + v.z + v.w;
#pragma unroll
    for (int o = 16; o > 0; o >>= 1) s += __shfl_down_sync(0xffffffffu, s, o);
    if ((tid & 31) == 0) wsum[tid >> 5] = s;
    __syncthreads();
    if (tid == 0) g_vsum[row] = wsum[0] + wsum[1] + wsum[2] + wsum[3];
}

// ---------------------------------------------------------------------------
// K2: u = sigmoid(y . zz + b_s) - 0.5, fp16.
// ---------------------------------------------------------------------------
__global__ __launch_bounds__(256) void k2_kernel(const float* __restrict__ bs) {
    __shared__ float ys[8][Ff];
    __shared__ float zs[Ff][132];

    const int tid = threadIdx.x;
    const int m0  = blockIdx.x * 128;
    const int n0  = blockIdx.y * 8;
    const int b   = blockIdx.z;

    if (tid < 128)
        ys[tid >> 4][tid & 15] = g_y[((size_t)b * Nn + n0) * Ff + tid];

    const float4* zz4 = reinterpret_cast<const float4*>(g_zz + ((size_t)b * Nn + m0) * Ff);
#pragma unroll
    for (int i = 0; i < 2; i++) {
        int q = tid + 256 * i;
        int m = q >> 2, fq = q & 3;
        float4 v = zz4[q];
        zs[fq * 4 + 0][m] = v.x;
        zs[fq * 4 + 1][m] = v.y;
        zs[fq * 4 + 2][m] = v.z;
        zs[fq * 4 + 3][m] = v.w;
    }
    __syncthreads();

    const int m4 = tid & 31, nq = tid >> 5;
    float4 acc = *reinterpret_cast<const float4*>(bs + (size_t)(n0 + nq) * Nn + m0 + m4 * 4);
#pragma unroll
    for (int f = 0; f < Ff; f++) {
        float yf = ys[nq][f];
        float4 z = *reinterpret_cast<const float4*>(&zs[f][m4 * 4]);
        acc.x += yf * z.x;
        acc.y += yf * z.y;
        acc.z += yf * z.z;
        acc.w += yf * z.w;
    }
    acc.x = 1.f / (1.f + __expf(-acc.x)) - 0.5f;
    acc.y = 1.f / (1.f + __expf(-acc.y)) - 0.5f;
    acc.z = 1.f / (1.f + __expf(-acc.z)) - 0.5f;
    acc.w = 1.f / (1.f + __expf(-acc.w)) - 0.5f;

    size_t base = ((size_t)b * Nn + n0 + nq) * Nn + m0;
    __half2* du = reinterpret_cast<__half2*>(g_sg_u + base) + m4 * 2;
    du[0] = __halves2half2(__float2half_rn(acc.x), __float2half_rn(acc.y));
    du[1] = __halves2half2(__float2half_rn(acc.z), __float2half_rn(acc.w));
}

// ---------------------------------------------------------------------------
// K3: s[b] = U[b] @ V_hi^T + 0.5*rowsumV  (single-pass fp16 HMMA).
//   128x64 tile / CTA, 8 warps (2x4), K chunks of 64, double buffer,
//   3 CTAs/SM (smem 55296 B/CTA, <=85 regs via launch_bounds).
// ---------------------------------------------------------------------------
#define K3_STRIDE 144
#define K3_A      0
#define K3_B      (128 * K3_STRIDE)            // 18432
#define K3_STAGE  (K3_B + 64 * K3_STRIDE)      // 27648
#define K3_SMEM   (2 * K3_STAGE)               // 55296

extern __shared__ char k3_smem[];

__global__ void __launch_bounds__(256, 3) k3_kernel(float* __restrict__ out) {
    const int tid  = threadIdx.x;
    const int wid  = tid >> 5;
    const int lane = tid & 31;
    const int i0   = blockIdx.x * 64;
    const int n0   = blockIdx.y * 128;
    const int b    = blockIdx.z;

    const uint32_t sbase = smem_u32(k3_smem);

    const __half* Au = g_sg_u + ((size_t)b * Nn + n0) * Nn;
    const __half* Bh = g_vs_hi + (size_t)i0 * Nn;

    const int wr = wid >> 2;   // 0..1 : row half (64 rows)
    const int wc = wid & 3;    // 0..3 : 16-col group

    const int am = lane >> 3;
    const uint32_t aoff = (uint32_t)(((am & 1) * 8 + (lane & 7)) * K3_STRIDE + (am >> 1) * 16)
                        + (uint32_t)(wr * 64 * K3_STRIDE);
    const int bg = lane >> 3;
    const uint32_t boff = (uint32_t)(((bg >> 1) * 8 + (lane & 7)) * K3_STRIDE + (bg & 1) * 16)
                        + (uint32_t)(wc * 16 * K3_STRIDE);

    float acc[4][2][4];
#pragma unroll
    for (int mi = 0; mi < 4; mi++)
#pragma unroll
        for (int ni = 0; ni < 2; ni++)
#pragma unroll
            for (int q = 0; q < 4; q++) acc[mi][ni][q] = 0.f;

#define K3_LOAD(CHUNK, STAGE)                                                      \
    do {                                                                           \
        const int k0_ = (CHUNK) * 64;                                              \
        const uint32_t st_ = sbase + (STAGE) * K3_STAGE;                           \
        _Pragma("unroll")                                                          \
        for (int i_ = 0; i_ < 4; i_++) {                                           \
            int idx_ = tid + 256 * i_;                                             \
            int row_ = idx_ >> 3, cc_ = idx_ & 7;                                  \
            uint32_t so_ = (uint32_t)(row_ * K3_STRIDE + cc_ * 16);                \
            cp16(st_ + K3_A + so_, Au + (size_t)row_ * Nn + k0_ + cc_ * 8);        \
        }                                                                          \
        _Pragma("unroll")                                                          \
        for (int i_ = 0; i_ < 2; i_++) {                                           \
            int idx_ = tid + 256 * i_;                                             \
            int row_ = idx_ >> 3, cc_ = idx_ & 7;                                  \
            uint32_t so_ = (uint32_t)(row_ * K3_STRIDE + cc_ * 16);                \
            cp16(st_ + K3_B + so_, Bh + (size_t)row_ * Nn + k0_ + cc_ * 8);        \
        }                                                                          \
        asm volatile("cp.async.commit_group;" ::: "memory");                       \
    } while (0)

    K3_LOAD(0, 0);

    for (int c = 0; c < 8; c++) {
        if (c + 1 < 8) {
            K3_LOAD(c + 1, (c + 1) & 1);
            asm volatile("cp.async.wait_group 1;" ::: "memory");
        } else {
            asm volatile("cp.async.wait_group 0;" ::: "memory");
        }
        __syncthreads();

        const uint32_t st  = sbase + (c & 1) * K3_STAGE;
        const uint32_t Aab = st + K3_A + aoff;
        const uint32_t Bab = st + K3_B + boff;

#pragma unroll
        for (int ks = 0; ks < 4; ks++) {
            const uint32_t kso = (uint32_t)(ks * 32);

            uint32_t bh[2][2];
            {
                uint32_t r[4];
                ldm_x4(r, Bab + kso);
                bh[0][0] = r[0]; bh[0][1] = r[1];
                bh[1][0] = r[2]; bh[1][1] = r[3];
            }
            uint32_t ah[4][4];
#pragma unroll
            for (int mi = 0; mi < 4; mi++)
                ldm_x4(ah[mi], Aab + (uint32_t)(mi * 16 * K3_STRIDE) + kso);

#pragma unroll
            for (int mi = 0; mi < 4; mi++)
#pragma unroll
                for (int ni = 0; ni < 2; ni++)
                    mma16816(acc[mi][ni], ah[mi], bh[ni]);
        }
        __syncthreads();
    }
#undef K3_LOAD

    // epilogue: add 0.5*rowsumV, write
    const int rr = lane >> 2;
    const int cc = (lane & 3) * 2;
#pragma unroll
    for (int ni = 0; ni < 2; ni++) {
        int col = i0 + wc * 16 + ni * 8 + cc;
        float v0 = 0.5f * g_vsum[col];
        float v1 = 0.5f * g_vsum[col + 1];
#pragma unroll
        for (int mi = 0; mi < 4; mi++) {
            int row = n0 + wr * 64 + mi * 16 + rr;
            float* p0 = out + ((size_t)b * Nn + row) * Nn + col;
            float* p1 = out + ((size_t)b * Nn + row + 8) * Nn + col;
            *reinterpret_cast<float2*>(p0) = make_float2(acc[mi][ni][0] + v0, acc[mi][ni][1] + v1);
            *reinterpret_cast<float2*>(p1) = make_float2(acc[mi][ni][2] + v0, acc[mi][ni][3] + v1);
        }
    }
}

// ---------------------------------------------------------------------------
// K4: in-place softmax over axis 1 (n) of d_out[b,n,i].
// ---------------------------------------------------------------------------
__global__ __launch_bounds__(256) void k4_kernel(float* __restrict__ out) {
    const int tid = threadIdx.x;
    const int col = tid & 31, seg = tid >> 5;
    const int i0  = blockIdx.x * 32;
    const int b   = blockIdx.y;

    float* base = out + (size_t)b * Nn * Nn + i0 + col;

    float m = -1e30f, s = 0.f;
    for (int n = seg * 64; n < seg * 64 + 64; n++) {
        float v  = base[(size_t)n * Nn];
        float mn = fmaxf(m, v);
        s = s * __expf(m - mn) + __expf(v - mn);
        m = mn;
    }

    __shared__ float sm[8][32], ssum[8][32];
    sm[seg][col]   = m;
    ssum[seg][col] = s;
    __syncthreads();

    float M = -1e30f;
#pragma unroll
    for (int g = 0; g < 8; g++) M = fmaxf(M, sm[g][col]);
    float S = 0.f;
#pragma unroll
    for (int g = 0; g < 8; g++) S += ssum[g][col] * __expf(sm[g][col] - M);
    float invS = 1.f / S;

    for (int n = seg * 64; n < seg * 64 + 64; n++) {
        float v = base[(size_t)n * Nn];
        base[(size_t)n * Nn] = __expf(v - M) * invS;
    }
}

// ---------------------------------------------------------------------------
extern "C" void kernel_launch(void* const* d_in, const int* in_sizes, int n_in,
                              void* d_out, int out_size) {
    const float* x  = (const float*)d_in[0];   // (64,512,16,288)
    const float* W1 = (const float*)d_in[1];   // (288,)
    const float* W2 = (const float*)d_in[2];   // (16,288)
    const float* W3 = (const float*)d_in[3];   // (16,)
    const float* bs = (const float*)d_in[4];   // (1,512,512)
    const float* Vs = (const float*)d_in[5];   // (512,512)
    float* out = (float*)d_out;                // (64,512,512)

    cudaFuncSetAttribute(k3_kernel, cudaFuncAttributeMaxDynamicSharedMemorySize, K3_SMEM);

    k1_kernel<<<Bb * Nn / 2, 288>>>(x, W1, W2, W3);
    kvs_kernel<<<Nn, 128>>>(Vs);
    k2_kernel<<<dim3(Nn / 128, Nn / 8, Bb), 256>>>(bs);
    k3_kernel<<<dim3(Nn / 64, Nn / 128, Bb), 256, K3_SMEM>>>(out);
    k4_kernel<<<dim3(Nn / 32, Bb), 256>>>(out);
}

// round 7
// speedup vs baseline: 2.4711x; 1.0145x over previous
#include <cuda_runtime.h>
#include <cuda_fp16.h>
#include <cstdint>

#define Bb 64
#define Nn 512
#define Ff 16
#define Tt 288

// ---------------- scratch (static device globals; no allocs) ----------------
__device__ float g_y [Bb * Nn * Ff];
__device__ float g_zz[Bb * Nn * Ff];
__device__ __half g_sg_u[(size_t)Bb * Nn * Nn];   // sigmoid(..) - 0.5, fp16
__device__ __half g_vs_hi[Nn * Nn];
__device__ float  g_vsum[Nn];                     // rowsum of V_s (fp32, exact)

// ------------------------------- PTX helpers --------------------------------
__device__ __forceinline__ uint32_t smem_u32(const void* p) {
    uint32_t a;
    asm("{ .reg .u64 t; cvta.to.shared.u64 t, %1; cvt.u32.u64 %0, t; }" : "=r"(a) : "l"(p));
    return a;
}
__device__ __forceinline__ void cp16(uint32_t dst, const void* src) {
    asm volatile("cp.async.cg.shared.global [%0], [%1], 16;" :: "r"(dst), "l"(src) : "memory");
}
__device__ __forceinline__ void ldm_x4(uint32_t* r, uint32_t addr) {
    asm volatile("ldmatrix.sync.aligned.m8n8.x4.shared.b16 {%0,%1,%2,%3}, [%4];"
                 : "=r"(r[0]), "=r"(r[1]), "=r"(r[2]), "=r"(r[3]) : "r"(addr));
}
__device__ __forceinline__ void mma16816(float* d, const uint32_t* a, const uint32_t* bb) {
    asm volatile(
        "mma.sync.aligned.m16n8k16.row.col.f32.f16.f16.f32 "
        "{%0,%1,%2,%3}, {%4,%5,%6,%7}, {%8,%9}, {%0,%1,%2,%3};"
        : "+f"(d[0]), "+f"(d[1]), "+f"(d[2]), "+f"(d[3])
        : "r"(a[0]), "r"(a[1]), "r"(a[2]), "r"(a[3]), "r"(bb[0]), "r"(bb[1]));
}

// ---------------------------------------------------------------------------
// K1: one WARP per bn. Zero smem, zero syncs, all-register accumulation.
//   lane L owns t in {L, L+32, ..., L+256}. Two dependency-free load streams
//   (x from DRAM, W2 from L1), butterfly reductions afterwards.
// ---------------------------------------------------------------------------
__global__ __launch_bounds__(256) void k1_kernel(const float* __restrict__ x,
                                                 const float* __restrict__ W1,
                                                 const float* __restrict__ W2,
                                                 const float* __restrict__ W3) {
    const int bn   = blockIdx.x * 8 + (threadIdx.x >> 5);
    const int lane = threadIdx.x & 31;

    const float* xp = x + (size_t)bn * (Ff * Tt);

    float w1l[9], rs[9];
#pragma unroll
    for (int j = 0; j < 9; j++) w1l[j] = W1[lane + 32 * j];
#pragma unroll
    for (int j = 0; j < 9; j++) rs[j] = 0.f;

    // stream x once: accumulate rs (per-lane) and y partials (per-f)
    float yp[Ff];
#pragma unroll
    for (int f = 0; f < Ff; f++) {
        const float w3f = __ldg(W3 + f);
        const float* xr = xp + f * Tt + lane;
        float acc = 0.f;
#pragma unroll
        for (int j = 0; j < 9; j++) {
            float xv = __ldg(xr + 32 * j);
            rs[j] = fmaf(xv, w3f, rs[j]);
            acc   = fmaf(xv, w1l[j], acc);
        }
        yp[f] = acc;
    }

    // stream W2 (L1-resident after first bn): zz partials
    float zp[Ff];
#pragma unroll
    for (int f = 0; f < Ff; f++) {
        const float* wr = W2 + f * Tt + lane;
        float acc = 0.f;
#pragma unroll
        for (int j = 0; j < 9; j++) acc = fmaf(__ldg(wr + 32 * j), rs[j], acc);
        zp[f] = acc;
    }

    // butterfly reductions; lane f keeps y[f], zz[f]
    float yv = 0.f, zzv = 0.f;
#pragma unroll
    for (int f = 0; f < Ff; f++) {
        float a = yp[f], z = zp[f];
#pragma unroll
        for (int o = 16; o > 0; o >>= 1) {
            a += __shfl_xor_sync(0xffffffffu, a, o);
            z += __shfl_xor_sync(0xffffffffu, z, o);
        }
        if (lane == f) { yv = a; zzv = z; }
    }
    if (lane < Ff) {
        g_y [(size_t)bn * Ff + lane] = yv;
        g_zz[(size_t)bn * Ff + lane] = zzv;
    }
}

// ---------------------------------------------------------------------------
// KVS: V_s row -> fp16 + exact fp32 rowsum. One block per row (i).
// ---------------------------------------------------------------------------
__global__ __launch_bounds__(128) void kvs_kernel(const float* __restrict__ Vs) {
    __shared__ float wsum[4];
    const int row = blockIdx.x;
    const int tid = threadIdx.x;

    float4 v = reinterpret_cast<const float4*>(Vs + (size_t)row * Nn)[tid];
    __half2* dst = reinterpret_cast<__half2*>(g_vs_hi + (size_t)row * Nn) + tid * 2;
    dst[0] = __halves2half2(__float2half_rn(v.x), __float2half_rn(v.y));
    dst[1] = __halves2half2(__float2half_rn(v.z), __float2half_rn(v.w));

    float s = v.x + v.y + v.z + v.w;
#pragma unroll
    for (int o = 16; o > 0; o >>= 1) s += __shfl_down_sync(0xffffffffu, s, o);
    if ((tid & 31) == 0) wsum[tid >> 5] = s;
    __syncthreads();
    if (tid == 0) g_vsum[row] = wsum[0] + wsum[1] + wsum[2] + wsum[3];
}

// ---------------------------------------------------------------------------
// K2: u = sigmoid(y . zz + b_s) - 0.5, fp16.
// ---------------------------------------------------------------------------
__global__ __launch_bounds__(256) void k2_kernel(const float* __restrict__ bs) {
    __shared__ float ys[8][Ff];
    __shared__ float zs[Ff][132];

    const int tid = threadIdx.x;
    const int m0  = blockIdx.x * 128;
    const int n0  = blockIdx.y * 8;
    const int b   = blockIdx.z;

    if (tid < 128)
        ys[tid >> 4][tid & 15] = g_y[((size_t)b * Nn + n0) * Ff + tid];

    const float4* zz4 = reinterpret_cast<const float4*>(g_zz + ((size_t)b * Nn + m0) * Ff);
#pragma unroll
    for (int i = 0; i < 2; i++) {
        int q = tid + 256 * i;
        int m = q >> 2, fq = q & 3;
        float4 v = zz4[q];
        zs[fq * 4 + 0][m] = v.x;
        zs[fq * 4 + 1][m] = v.y;
        zs[fq * 4 + 2][m] = v.z;
        zs[fq * 4 + 3][m] = v.w;
    }
    __syncthreads();

    const int m4 = tid & 31, nq = tid >> 5;
    float4 acc = *reinterpret_cast<const float4*>(bs + (size_t)(n0 + nq) * Nn + m0 + m4 * 4);
#pragma unroll
    for (int f = 0; f < Ff; f++) {
        float yf = ys[nq][f];
        float4 z = *reinterpret_cast<const float4*>(&zs[f][m4 * 4]);
        acc.x += yf * z.x;
        acc.y += yf * z.y;
        acc.z += yf * z.z;
        acc.w += yf * z.w;
    }
    acc.x = 1.f / (1.f + __expf(-acc.x)) - 0.5f;
    acc.y = 1.f / (1.f + __expf(-acc.y)) - 0.5f;
    acc.z = 1.f / (1.f + __expf(-acc.z)) - 0.5f;
    acc.w = 1.f / (1.f + __expf(-acc.w)) - 0.5f;

    size_t base = ((size_t)b * Nn + n0 + nq) * Nn + m0;
    __half2* du = reinterpret_cast<__half2*>(g_sg_u + base) + m4 * 2;
    du[0] = __halves2half2(__float2half_rn(acc.x), __float2half_rn(acc.y));
    du[1] = __halves2half2(__float2half_rn(acc.z), __float2half_rn(acc.w));
}

// ---------------------------------------------------------------------------
// K3: s[b] = U[b] @ V_hi^T + 0.5*rowsumV  (single-pass fp16 HMMA).
//   128x128 tile / CTA, 8 warps (2x4), K chunks of 64, double buffer,
//   2 CTAs/SM.
// ---------------------------------------------------------------------------
#define K3_STRIDE 144
#define K3_A      0
#define K3_B      (128 * K3_STRIDE)            // 18432
#define K3_STAGE  (2 * 128 * K3_STRIDE)        // 36864
#define K3_SMEM   (2 * K3_STAGE)               // 73728

extern __shared__ char k3_smem[];

__global__ void __launch_bounds__(256, 2) k3_kernel(float* __restrict__ out) {
    const int tid  = threadIdx.x;
    const int wid  = tid >> 5;
    const int lane = tid & 31;
    const int i0   = blockIdx.x * 128;
    const int n0   = blockIdx.y * 128;
    const int b    = blockIdx.z;

    const uint32_t sbase = smem_u32(k3_smem);

    const __half* Au = g_sg_u + ((size_t)b * Nn + n0) * Nn;
    const __half* Bh = g_vs_hi + (size_t)i0 * Nn;

    const int wr = wid >> 2;   // 0..1 : row half (64 rows)
    const int wc = wid & 3;    // 0..3 : 32-col group

    const int am = lane >> 3;
    const uint32_t aoff = (uint32_t)(((am & 1) * 8 + (lane & 7)) * K3_STRIDE + (am >> 1) * 16)
                        + (uint32_t)(wr * 64 * K3_STRIDE);
    const int bg = lane >> 3;
    const uint32_t boff = (uint32_t)(((bg >> 1) * 8 + (lane & 7)) * K3_STRIDE + (bg & 1) * 16)
                        + (uint32_t)(wc * 32 * K3_STRIDE);

    float acc[4][4][4];
#pragma unroll
    for (int mi = 0; mi < 4; mi++)
#pragma unroll
        for (int ni = 0; ni < 4; ni++)
#pragma unroll
            for (int q = 0; q < 4; q++) acc[mi][ni][q] = 0.f;

#define K3_LOAD(CHUNK, STAGE)                                                      \
    do {                                                                           \
        const int k0_ = (CHUNK) * 64;                                              \
        const uint32_t st_ = sbase + (STAGE) * K3_STAGE;                           \
        _Pragma("unroll")                                                          \
        for (int i_ = 0; i_ < 4; i_++) {                                           \
            int idx_ = tid + 256 * i_;                                             \
            int row_ = idx_ >> 3, cc_ = idx_ & 7;                                  \
            uint32_t so_ = (uint32_t)(row_ * K3_STRIDE + cc_ * 16);                \
            cp16(st_ + K3_A + so_, Au + (size_t)row_ * Nn + k0_ + cc_ * 8);        \
            cp16(st_ + K3_B + so_, Bh + (size_t)row_ * Nn + k0_ + cc_ * 8);        \
        }                                                                          \
        asm volatile("cp.async.commit_group;" ::: "memory");                       \
    } while (0)

    K3_LOAD(0, 0);

    for (int c = 0; c < 8; c++) {
        if (c + 1 < 8) {
            K3_LOAD(c + 1, (c + 1) & 1);
            asm volatile("cp.async.wait_group 1;" ::: "memory");
        } else {
            asm volatile("cp.async.wait_group 0;" ::: "memory");
        }
        __syncthreads();

        const uint32_t st  = sbase + (c & 1) * K3_STAGE;
        const uint32_t Aab = st + K3_A + aoff;
        const uint32_t Bab = st + K3_B + boff;

#pragma unroll
        for (int ks = 0; ks < 4; ks++) {
            const uint32_t kso = (uint32_t)(ks * 32);

            uint32_t ah[4][4];
#pragma unroll
            for (int mi = 0; mi < 4; mi++)
                ldm_x4(ah[mi], Aab + (uint32_t)(mi * 16 * K3_STRIDE) + kso);

            uint32_t bh[4][2];
#pragma unroll
            for (int dn = 0; dn < 2; dn++) {
                uint32_t r[4];
                ldm_x4(r, Bab + (uint32_t)(dn * 16 * K3_STRIDE) + kso);
                bh[2 * dn][0] = r[0]; bh[2 * dn][1] = r[1];
                bh[2 * dn + 1][0] = r[2]; bh[2 * dn + 1][1] = r[3];
            }

#pragma unroll
            for (int mi = 0; mi < 4; mi++)
#pragma unroll
                for (int ni = 0; ni < 4; ni++)
                    mma16816(acc[mi][ni], ah[mi], bh[ni]);
        }
        __syncthreads();
    }
#undef K3_LOAD

    // epilogue: add 0.5*rowsumV, write
    const int rr = lane >> 2;
    const int cc = (lane & 3) * 2;
#pragma unroll
    for (int ni = 0; ni < 4; ni++) {
        int col = i0 + wc * 32 + ni * 8 + cc;
        float v0 = 0.5f * g_vsum[col];
        float v1 = 0.5f * g_vsum[col + 1];
#pragma unroll
        for (int mi = 0; mi < 4; mi++) {
            int row = n0 + wr * 64 + mi * 16 + rr;
            float* p0 = out + ((size_t)b * Nn + row) * Nn + col;
            float* p1 = out + ((size_t)b * Nn + row + 8) * Nn + col;
            *reinterpret_cast<float2*>(p0) = make_float2(acc[mi][ni][0] + v0, acc[mi][ni][1] + v1);
            *reinterpret_cast<float2*>(p1) = make_float2(acc[mi][ni][2] + v0, acc[mi][ni][3] + v1);
        }
    }
}

// ---------------------------------------------------------------------------
// K4: in-place softmax over axis 1 (n) of d_out[b,n,i].
// ---------------------------------------------------------------------------
__global__ __launch_bounds__(256) void k4_kernel(float* __restrict__ out) {
    const int tid = threadIdx.x;
    const int col = tid & 31, seg = tid >> 5;
    const int i0  = blockIdx.x * 32;
    const int b   = blockIdx.y;

    float* base = out + (size_t)b * Nn * Nn + i0 + col;

    float m = -1e30f, s = 0.f;
    for (int n = seg * 64; n < seg * 64 + 64; n++) {
        float v  = base[(size_t)n * Nn];
        float mn = fmaxf(m, v);
        s = s * __expf(m - mn) + __expf(v - mn);
        m = mn;
    }

    __shared__ float sm[8][32], ssum[8][32];
    sm[seg][col]   = m;
    ssum[seg][col] = s;
    __syncthreads();

    float M = -1e30f;
#pragma unroll
    for (int g = 0; g < 8; g++) M = fmaxf(M, sm[g][col]);
    float S = 0.f;
#pragma unroll
    for (int g = 0; g < 8; g++) S += ssum[g][col] * __expf(sm[g][col] - M);
    float invS = 1.f / S;

    for (int n = seg * 64; n < seg * 64 + 64; n++) {
        float v = base[(size_t)n * Nn];
        base[(size_t)n * Nn] = __expf(v - M) * invS;
    }
}

// ---------------------------------------------------------------------------
extern "C" void kernel_launch(void* const* d_in, const int* in_sizes, int n_in,
                              void* d_out, int out_size) {
    const float* x  = (const float*)d_in[0];   // (64,512,16,288)
    const float* W1 = (const float*)d_in[1];   // (288,)
    const float* W2 = (const float*)d_in[2];   // (16,288)
    const float* W3 = (const float*)d_in[3];   // (16,)
    const float* bs = (const float*)d_in[4];   // (1,512,512)
    const float* Vs = (const float*)d_in[5];   // (512,512)
    float* out = (float*)d_out;                // (64,512,512)

    cudaFuncSetAttribute(k3_kernel, cudaFuncAttributeMaxDynamicSharedMemorySize, K3_SMEM);

    k1_kernel<<<Bb * Nn / 8, 256>>>(x, W1, W2, W3);
    kvs_kernel<<<Nn, 128>>>(Vs);
    k2_kernel<<<dim3(Nn / 128, Nn / 8, Bb), 256>>>(bs);
    k3_kernel<<<dim3(Nn / 128, Nn / 128, Bb), 256, K3_SMEM>>>(out);
    k4_kernel<<<dim3(Nn / 32, Bb), 256>>>(out);
}